// round 10
// baseline (speedup 1.0000x reference)
#include <cuda_runtime.h>
#include <cuda_bf16.h>
#include <math.h>
#include <stdint.h>

#define Bb 8
#define Cc 1536
#define Tt 4096
#define Aa 128
#define K3 (3*Cc)   // 4608

// ---- warp-MMA logits GEMM config ----
#define BKC 32              // K per chunk
#define NCH (K3/BKC)        // 144
#define A_STR 36            // W1 tile [128 a][k] stride (conflict-free frags)
#define B_STR 136           // attn tile [32 k][t] stride (conflict-free frags)
#define ABUF (128*A_STR)    // 4608 floats
#define BBUF (BKC*B_STR)    // 4352 floats
// double-buffered As/Bs + red
#define SMEM_LOGITS ((2*(ABUF + BBUF) + 4*128)*4)   // 73728 B

// Scratch (allocation-free rule: __device__ globals)
static __device__ __nv_bfloat162 g_ms[(size_t)Bb*Cc*Tt];  // packed (mean, std)
static __device__ float g_logits[Bb*Tt];
static __device__ float g_e[Bb*Tt];
static __device__ float g_iZ[Bb*Tt];       // 1 / cumsum(e)

__device__ __forceinline__ float f2tf32(float f) {
    uint32_t r;
    asm("cvt.rna.tf32.f32 %0, %1;" : "=r"(r) : "f"(f));
    return __uint_as_float(r);
}

__device__ __forceinline__ void mma_tf32(float* d, const float* a, const float* b)
{
    asm volatile(
        "mma.sync.aligned.m16n8k8.row.col.f32.tf32.tf32.f32 "
        "{%0,%1,%2,%3}, {%4,%5,%6,%7}, {%8,%9}, {%0,%1,%2,%3};"
        : "+f"(d[0]), "+f"(d[1]), "+f"(d[2]), "+f"(d[3])
        : "r"(__float_as_uint(a[0])), "r"(__float_as_uint(a[1])),
          "r"(__float_as_uint(a[2])), "r"(__float_as_uint(a[3])),
          "r"(__float_as_uint(b[0])), "r"(__float_as_uint(b[1])));
}

// Robust lengths read (reference declares int64; JAX w/o x64 emits int32).
__device__ __forceinline__ int load_length(const void* lp, int b)
{
    const int* w = (const int*)lp;
    bool is64 = true;
#pragma unroll
    for (int i = 0; i < 4; i++)
        if (w[2*i + 1] != 0) is64 = false;
    if (is64) return (int)((const long long*)lp)[b];
    return w[b];
}

// Exclusive block scan, NW warps (NW*32 threads). ws: >= NW floats smem.
template<int NW>
__device__ __forceinline__ float block_excl_scan(float v, float* ws)
{
    int lane = threadIdx.x & 31;
    int warp = threadIdx.x >> 5;
    float incl = v;
#pragma unroll
    for (int d = 1; d < 32; d <<= 1) {
        float n = __shfl_up_sync(0xffffffffu, incl, d);
        if (lane >= d) incl += n;
    }
    __syncthreads();
    if (lane == 31) ws[warp] = incl;
    __syncthreads();
    if (warp == 0) {
        float wv = (lane < NW) ? ws[lane] : 0.f;
        float wi = wv;
#pragma unroll
        for (int d = 1; d < NW; d <<= 1) {
            float n = __shfl_up_sync(0xffffffffu, wi, d);
            if (lane >= d) wi += n;
        }
        if (lane < NW) ws[lane] = wi - wv;
    }
    __syncthreads();
    return ws[warp] + (incl - v);
}

// ---------------- Kernel 1: causal mean / std (512 thr x 8 elems, bf16x2 out) ----------------
__global__ void __launch_bounds__(512, 3) stats_kernel(const float* __restrict__ x,
                                                       const void* __restrict__ lengths)
{
    int c = blockIdx.x, b = blockIdx.y;
    size_t roff = ((size_t)b*Cc + c)*(size_t)Tt;
    const float4* row4 = (const float4*)(x + roff);
    uint4* ms4 = (uint4*)(g_ms + roff);
    int len = load_length(lengths, b);
    __shared__ float ws[16];
    int tid = threadIdx.x;
    int base = tid * 8;

    float xv[8];
#pragma unroll
    for (int q = 0; q < 2; q++) {
        float4 f = row4[tid*2 + q];
        xv[q*4+0]=f.x; xv[q*4+1]=f.y; xv[q*4+2]=f.z; xv[q*4+3]=f.w;
    }
    float c1 = 0.f, c2 = 0.f;
#pragma unroll
    for (int j = 0; j < 8; j++) {
        float v = (base + j < len) ? xv[j] : 0.f;
        c1 += v; c2 += v*v;
    }
    float o1 = block_excl_scan<16>(c1, ws);
    float o2 = block_excl_scan<16>(c2, ws);

    float r1 = 0.f, r2 = 0.f;
#pragma unroll
    for (int q = 0; q < 2; q++) {
        uint4 pk;
        uint32_t* pw = (uint32_t*)&pk;
#pragma unroll
        for (int j = 0; j < 4; j++) {
            int jj = q*4 + j;
            int t = base + jj;
            float v = (t < len) ? xv[jj] : 0.f;
            r1 += v; r2 += v*v;
            int cn = (t + 1 < len) ? (t + 1) : len;
            float cnt = (cn < 1) ? 1.f : (float)cn;
            float m = (o1 + r1) / cnt;
            float var = (o2 + r2) / cnt - m*m;
            float sd = sqrtf(fmaxf(var, 1e-12f));
            __nv_bfloat162 h;
            h.x = __float2bfloat16_rn(m);
            h.y = __float2bfloat16_rn(sd);
            pw[j] = *(uint32_t*)&h;
        }
        ms4[tid*2 + q] = pk;
    }
}

// ---------------- Kernel 2: logits via warp TF32 MMA, double-buffered pipeline ----------------
// D[a=128][t=128] = W1[a,k] . attn[k,t]; warp grid 4(a) x 2(t), warp tile 32x64.
// Ping-pong As/Bs: ONE __syncthreads per chunk; global loads for ch+1 issued
// before the MMA on ch so their latency hides under tensor work.
__global__ void __launch_bounds__(256, 2) logits_mma_kernel(const float* __restrict__ x,
                                                            const float* __restrict__ W1,
                                                            const float* __restrict__ b1,
                                                            const float* __restrict__ W2,
                                                            const float* __restrict__ b2)
{
    extern __shared__ float sm[];
    float* AsB[2] = { sm,               sm + ABUF };
    float* BsB[2] = { sm + 2*ABUF,      sm + 2*ABUF + BBUF };
    float* red    = sm + 2*(ABUF + BBUF);   // [4][128]

    int tid  = threadIdx.x;
    int lane = tid & 31;
    int wid  = tid >> 5;
    int g    = lane >> 2;     // group 0..7
    int tig  = lane & 3;      // thread-in-group
    int wm   = wid >> 1;      // a quadrant 0..3
    int wn   = wid & 1;       // t half 0..1
    int b    = blockIdx.y;
    int t0   = blockIdx.x * 128;

    // Producer mappings
    int pa  = tid >> 1;            // W1: a row
    int pkh = (tid & 1) * 16;      // W1: k half
    int pk  = tid >> 3;            // attn: k row 0..31
    int pt8 = tid & 7;             // attn: 16B lane

    float acc[2][8][4];
#pragma unroll
    for (int mi = 0; mi < 2; mi++)
#pragma unroll
        for (int ni = 0; ni < 8; ni++)
#pragma unroll
            for (int r = 0; r < 4; r++) acc[mi][ni][r] = 0.f;

    uint4  ast[4];   // attn staging
    float4 wv[4];    // W1 staging

    auto stage = [&](int ch) {
        int k0 = ch * BKC;
        if (k0 < Cc) {
            const uint4* p = (const uint4*)(x + ((size_t)b*Cc + k0 + pk)*(size_t)Tt + t0);
#pragma unroll
            for (int q = 0; q < 4; q++) ast[q] = __ldg(p + pt8 + q*8);
        } else {
            int crow = (k0 < 2*Cc) ? (k0 - Cc) : (k0 - 2*Cc);
            const uint4* p = (const uint4*)(g_ms + ((size_t)b*Cc + crow + pk)*(size_t)Tt + t0);
#pragma unroll
            for (int q = 0; q < 4; q++) ast[q] = __ldg(p + pt8 + q*8);
        }
        const float4* wrow = (const float4*)(W1 + (size_t)pa*K3 + k0 + pkh);
#pragma unroll
        for (int q = 0; q < 4; q++) wv[q] = __ldg(wrow + q);
    };

    auto emit = [&](int ch, float* As, float* Bs) {
        int k0 = ch * BKC;
        if (k0 < Cc) {
#pragma unroll
            for (int q = 0; q < 4; q++) {
                float4 f = *(float4*)&ast[q];
                float* d = &Bs[pk*B_STR + (pt8 + q*8)*4];
                d[0] = f2tf32(f.x); d[1] = f2tf32(f.y);
                d[2] = f2tf32(f.z); d[3] = f2tf32(f.w);
            }
        } else {
            bool hi = (k0 >= 2*Cc);   // std lives in the high half
#pragma unroll
            for (int q = 0; q < 4; q++) {
                const __nv_bfloat162* h = (const __nv_bfloat162*)&ast[q];
                float* d = &Bs[pk*B_STR + (pt8 + q*8)*4];
#pragma unroll
                for (int j = 0; j < 4; j++) {
                    float v = hi ? __high2float(h[j]) : __low2float(h[j]);
                    d[j] = f2tf32(v);
                }
            }
        }
#pragma unroll
        for (int q = 0; q < 4; q++) {
            float* d = &As[pa*A_STR + pkh + q*4];
            d[0] = f2tf32(wv[q].x); d[1] = f2tf32(wv[q].y);
            d[2] = f2tf32(wv[q].z); d[3] = f2tf32(wv[q].w);
        }
    };

    // Prologue: fill buffer 0
    stage(0);
    emit(0, AsB[0], BsB[0]);
    __syncthreads();

    for (int ch = 0; ch < NCH; ch++) {
        // Issue next chunk's global loads early (latency hides under MMA)
        if (ch + 1 < NCH) stage(ch + 1);

        const float* As = AsB[ch & 1];
        const float* Bs = BsB[ch & 1];
#pragma unroll
        for (int ks = 0; ks < 4; ks++) {
            int kb = ks * 8;
            float a_fr[2][4];
#pragma unroll
            for (int mi = 0; mi < 2; mi++) {
                int ar = wm*32 + mi*16;
                a_fr[mi][0] = As[(ar + g    )*A_STR + kb + tig];
                a_fr[mi][1] = As[(ar + 8 + g)*A_STR + kb + tig];
                a_fr[mi][2] = As[(ar + g    )*A_STR + kb + tig + 4];
                a_fr[mi][3] = As[(ar + 8 + g)*A_STR + kb + tig + 4];
            }
            float b_fr[8][2];
#pragma unroll
            for (int ni = 0; ni < 8; ni++) {
                int t = wn*64 + ni*8 + g;
                b_fr[ni][0] = Bs[(kb + tig    )*B_STR + t];
                b_fr[ni][1] = Bs[(kb + tig + 4)*B_STR + t];
            }
#pragma unroll
            for (int mi = 0; mi < 2; mi++)
#pragma unroll
                for (int ni = 0; ni < 8; ni++)
                    mma_tf32(acc[mi][ni], a_fr[mi], b_fr[ni]);
        }

        // Store ch+1 into the other buffer (its last consumer finished at ch-1,
        // protected by the previous iteration's barrier)
        if (ch + 1 < NCH) emit(ch + 1, AsB[(ch + 1) & 1], BsB[(ch + 1) & 1]);
        __syncthreads();
    }

    // Epilogue: tanh + W2 dot over a, reduce to logits[t]
    float part[16];
#pragma unroll
    for (int i = 0; i < 16; i++) part[i] = 0.f;
#pragma unroll
    for (int mi = 0; mi < 2; mi++) {
        int abase = wm*32 + mi*16;
        float b1a = __ldg(b1 + abase + g),     w2a = __ldg(W2 + abase + g);
        float b1b = __ldg(b1 + abase + 8 + g), w2b = __ldg(W2 + abase + 8 + g);
#pragma unroll
        for (int ni = 0; ni < 8; ni++) {
            part[ni*2+0] += w2a*tanhf(acc[mi][ni][0] + b1a) + w2b*tanhf(acc[mi][ni][2] + b1b);
            part[ni*2+1] += w2a*tanhf(acc[mi][ni][1] + b1a) + w2b*tanhf(acc[mi][ni][3] + b1b);
        }
    }
#pragma unroll
    for (int o = 4; o <= 16; o <<= 1)
#pragma unroll
        for (int i = 0; i < 16; i++)
            part[i] += __shfl_xor_sync(0xffffffffu, part[i], o);
    if (lane < 4) {
#pragma unroll
        for (int ni = 0; ni < 8; ni++) {
            red[wm*128 + wn*64 + ni*8 + lane*2 + 0] = part[ni*2+0];
            red[wm*128 + wn*64 + ni*8 + lane*2 + 1] = part[ni*2+1];
        }
    }
    __syncthreads();
    if (tid < 128) {
        float s = red[tid] + red[128 + tid] + red[256 + tid] + red[384 + tid];
        g_logits[b*Tt + t0 + tid] = s + __ldg(b2);
    }
}

// ---------------- Kernel 3: per-batch max, e = exp(l - max), iZ = 1/cumsum(e) ----------------
__global__ void __launch_bounds__(256) softmax_kernel()
{
    int b = blockIdx.x;
    __shared__ float ls[Tt];
    __shared__ float ws[8];
    __shared__ float red[8];
    int tid = threadIdx.x;
    int lane = tid & 31, warp = tid >> 5;

    float mx = -3.4e38f;
    for (int i = tid; i < Tt; i += 256) {
        float v = g_logits[b*Tt + i];
        ls[i] = v;
        mx = fmaxf(mx, v);
    }
#pragma unroll
    for (int d = 16; d; d >>= 1) mx = fmaxf(mx, __shfl_xor_sync(0xffffffffu, mx, d));
    if (lane == 0) red[warp] = mx;
    __syncthreads();
    if (tid == 0) {
        float m = red[0];
        for (int i = 1; i < 8; i++) m = fmaxf(m, red[i]);
        red[0] = m;
    }
    __syncthreads();
    mx = red[0];

    int base = tid * 16;
    float ev[16], l1[16];
    float c1 = 0.f;
#pragma unroll
    for (int j = 0; j < 16; j++) {
        float e = expf(ls[base + j] - mx);
        ev[j] = e; c1 += e; l1[j] = c1;
    }
    float o1 = block_excl_scan<8>(c1, ws);
    float4* e4 = (float4*)(g_e  + b*Tt + base);
    float4* z4 = (float4*)(g_iZ + b*Tt + base);
#pragma unroll
    for (int q = 0; q < 4; q++) {
        e4[q] = make_float4(ev[q*4], ev[q*4+1], ev[q*4+2], ev[q*4+3]);
        z4[q] = make_float4(1.f/(o1+l1[q*4]),   1.f/(o1+l1[q*4+1]),
                            1.f/(o1+l1[q*4+2]), 1.f/(o1+l1[q*4+3]));
    }
}

// ---------------- Kernel 4: weighted pooling (512 thr x 8 elems) ----------------
__global__ void __launch_bounds__(512, 3) pool_kernel(const float* __restrict__ x,
                                                      float* __restrict__ out)
{
    int c = blockIdx.x, b = blockIdx.y;
    size_t roff = ((size_t)b*Cc + c)*(size_t)Tt;
    int tid = threadIdx.x;
    __shared__ float ws[16];
    __shared__ float red[16];
    int lane = tid & 31, warp = tid >> 5;

    const float4* x4 = (const float4*)(x + roff);
    const float4* e4 = (const float4*)(g_e  + b*Tt);
    const float4* z4 = (const float4*)(g_iZ + b*Tt);

    float xv[8], ev[8], zv[8];
#pragma unroll
    for (int q = 0; q < 2; q++) {
        float4 f = x4[tid*2 + q]; xv[q*4]=f.x; xv[q*4+1]=f.y; xv[q*4+2]=f.z; xv[q*4+3]=f.w;
        f = e4[tid*2 + q];        ev[q*4]=f.x; ev[q*4+1]=f.y; ev[q*4+2]=f.z; ev[q*4+3]=f.w;
        f = z4[tid*2 + q];        zv[q*4]=f.x; zv[q*4+1]=f.y; zv[q*4+2]=f.z; zv[q*4+3]=f.w;
    }

    float c1 = 0.f;
#pragma unroll
    for (int j = 0; j < 8; j++) c1 += ev[j]*xv[j];
    float o1 = block_excl_scan<16>(c1, ws);

    float sum_wm = 0.f, c2 = 0.f;
    {
        float r1 = 0.f;
#pragma unroll
        for (int j = 0; j < 8; j++) {
            r1 += ev[j]*xv[j];
            float wm = (o1 + r1) * zv[j];     // zv holds 1/Z
            sum_wm += wm;
            float d = xv[j] - wm;
            c2 += ev[j]*d*d;
        }
    }
    float o2 = block_excl_scan<16>(c2, ws);

    float sum_ws = 0.f;
    {
        float r1 = 0.f, r2 = 0.f;
#pragma unroll
        for (int j = 0; j < 8; j++) {
            r1 += ev[j]*xv[j];
            float wm = (o1 + r1) * zv[j];
            float d = xv[j] - wm;
            r2 += ev[j]*d*d;
            float wv = (o2 + r2) * zv[j];
            sum_ws += sqrtf(fmaxf(wv, 1e-12f));
        }
    }

#pragma unroll
    for (int d = 16; d; d >>= 1) {
        sum_wm += __shfl_xor_sync(0xffffffffu, sum_wm, d);
        sum_ws += __shfl_xor_sync(0xffffffffu, sum_ws, d);
    }
    if (lane == 0) red[warp] = sum_wm;
    __syncthreads();
    if (tid == 0) {
        float tot_m = 0.f;
        for (int i = 0; i < 16; i++) tot_m += red[i];
        red[0] = tot_m;
    }
    __syncthreads();
    float tot_m = red[0];
    __syncthreads();
    if (lane == 0) red[warp] = sum_ws;
    __syncthreads();
    if (tid == 0) {
        float tot_s = 0.f;
        for (int i = 0; i < 16; i++) tot_s += red[i];
        const float fw = (float)(1.0 / (4096.0 + 1e-12));
        out[(size_t)b*(2*Cc) + c]      = tot_m * fw;
        out[(size_t)b*(2*Cc) + Cc + c] = tot_s * fw;
    }
}

extern "C" void kernel_launch(void* const* d_in, const int* in_sizes, int n_in,
                              void* d_out, int out_size)
{
    const float* x       = (const float*)d_in[0];
    const void*  lengths = d_in[1];            // int32 or int64, auto-detected
    const float* W1      = (const float*)d_in[2];
    const float* b1      = (const float*)d_in[3];
    const float* W2      = (const float*)d_in[4];
    const float* b2      = (const float*)d_in[5];
    float* out = (float*)d_out;

    // Idempotent, host-side, not a captured op.
    cudaFuncSetAttribute(logits_mma_kernel,
                         cudaFuncAttributeMaxDynamicSharedMemorySize, SMEM_LOGITS);

    dim3 gs(Cc, Bb);
    stats_kernel<<<gs, 512>>>(x, lengths);
    dim3 gl(Tt / 128, Bb);
    logits_mma_kernel<<<gl, 256, SMEM_LOGITS>>>(x, W1, b1, W2, b2);
    softmax_kernel<<<Bb, 256>>>();
    pool_kernel<<<gs, 512>>>(x, out);
}

// round 11
// speedup vs baseline: 1.1987x; 1.1987x over previous
#include <cuda_runtime.h>
#include <cuda_bf16.h>
#include <math.h>
#include <stdint.h>

#define Bb 8
#define Cc 1536
#define Tt 4096
#define Aa 128
#define K3 (3*Cc)   // 4608

// ---- warp-MMA logits GEMM config ----
#define BKC 32              // K per chunk
#define NCH (K3/BKC)        // 144
#define A_STR 36            // W1 tile [128 a][k] stride (conflict-free frags)
#define B_STR 136           // attn tile [32 k][t] stride (conflict-free frags)
#define ABUF (128*A_STR)    // 4608 floats
#define BBUF (BKC*B_STR)    // 4352 floats
// double-buffered As (cp.async) + single Bs + red
#define SMEM_LOGITS ((2*ABUF + BBUF + 4*128)*4)   // 56320 B

// Scratch (allocation-free rule: __device__ globals)
static __device__ __nv_bfloat162 g_ms[(size_t)Bb*Cc*Tt];  // packed (mean, std)
static __device__ float g_logits[Bb*Tt];
static __device__ float g_e[Bb*Tt];
static __device__ float g_iZ[Bb*Tt];       // 1 / cumsum(e)

__device__ __forceinline__ float f2tf32(float f) {
    uint32_t r;
    asm("cvt.rna.tf32.f32 %0, %1;" : "=r"(r) : "f"(f));
    return __uint_as_float(r);
}

__device__ __forceinline__ uint32_t smem_u32(const void* p) {
    uint32_t a;
    asm("{ .reg .u64 t; cvta.to.shared.u64 t, %1; cvt.u32.u64 %0, t; }" : "=r"(a) : "l"(p));
    return a;
}

__device__ __forceinline__ void cp_async16(uint32_t s, const void* g) {
    asm volatile("cp.async.ca.shared.global [%0], [%1], 16;" :: "r"(s), "l"(g));
}
__device__ __forceinline__ void cp_commit() {
    asm volatile("cp.async.commit_group;");
}
template<int N>
__device__ __forceinline__ void cp_wait() {
    asm volatile("cp.async.wait_group %0;" :: "n"(N));
}

__device__ __forceinline__ void mma_tf32(float* d, const float* a, const float* b)
{
    asm volatile(
        "mma.sync.aligned.m16n8k8.row.col.f32.tf32.tf32.f32 "
        "{%0,%1,%2,%3}, {%4,%5,%6,%7}, {%8,%9}, {%0,%1,%2,%3};"
        : "+f"(d[0]), "+f"(d[1]), "+f"(d[2]), "+f"(d[3])
        : "r"(__float_as_uint(a[0])), "r"(__float_as_uint(a[1])),
          "r"(__float_as_uint(a[2])), "r"(__float_as_uint(a[3])),
          "r"(__float_as_uint(b[0])), "r"(__float_as_uint(b[1])));
}

// Robust lengths read (reference declares int64; JAX w/o x64 emits int32).
__device__ __forceinline__ int load_length(const void* lp, int b)
{
    const int* w = (const int*)lp;
    bool is64 = true;
#pragma unroll
    for (int i = 0; i < 4; i++)
        if (w[2*i + 1] != 0) is64 = false;
    if (is64) return (int)((const long long*)lp)[b];
    return w[b];
}

// Exclusive block scan, NW warps (NW*32 threads). ws: >= NW floats smem.
template<int NW>
__device__ __forceinline__ float block_excl_scan(float v, float* ws)
{
    int lane = threadIdx.x & 31;
    int warp = threadIdx.x >> 5;
    float incl = v;
#pragma unroll
    for (int d = 1; d < 32; d <<= 1) {
        float n = __shfl_up_sync(0xffffffffu, incl, d);
        if (lane >= d) incl += n;
    }
    __syncthreads();
    if (lane == 31) ws[warp] = incl;
    __syncthreads();
    if (warp == 0) {
        float wv = (lane < NW) ? ws[lane] : 0.f;
        float wi = wv;
#pragma unroll
        for (int d = 1; d < NW; d <<= 1) {
            float n = __shfl_up_sync(0xffffffffu, wi, d);
            if (lane >= d) wi += n;
        }
        if (lane < NW) ws[lane] = wi - wv;
    }
    __syncthreads();
    return ws[warp] + (incl - v);
}

// ---------------- Kernel 1: causal mean / std (512 thr x 8 elems, bf16x2 out) ----------------
__global__ void __launch_bounds__(512, 3) stats_kernel(const float* __restrict__ x,
                                                       const void* __restrict__ lengths)
{
    int c = blockIdx.x, b = blockIdx.y;
    size_t roff = ((size_t)b*Cc + c)*(size_t)Tt;
    const float4* row4 = (const float4*)(x + roff);
    uint4* ms4 = (uint4*)(g_ms + roff);
    int len = load_length(lengths, b);
    __shared__ float ws[16];
    int tid = threadIdx.x;
    int base = tid * 8;

    float xv[8];
#pragma unroll
    for (int q = 0; q < 2; q++) {
        float4 f = row4[tid*2 + q];
        xv[q*4+0]=f.x; xv[q*4+1]=f.y; xv[q*4+2]=f.z; xv[q*4+3]=f.w;
    }
    float c1 = 0.f, c2 = 0.f;
#pragma unroll
    for (int j = 0; j < 8; j++) {
        float v = (base + j < len) ? xv[j] : 0.f;
        c1 += v; c2 += v*v;
    }
    float o1 = block_excl_scan<16>(c1, ws);
    float o2 = block_excl_scan<16>(c2, ws);

    float r1 = 0.f, r2 = 0.f;
#pragma unroll
    for (int q = 0; q < 2; q++) {
        uint4 pk;
        uint32_t* pw = (uint32_t*)&pk;
#pragma unroll
        for (int j = 0; j < 4; j++) {
            int jj = q*4 + j;
            int t = base + jj;
            float v = (t < len) ? xv[jj] : 0.f;
            r1 += v; r2 += v*v;
            int cn = (t + 1 < len) ? (t + 1) : len;
            float cnt = (cn < 1) ? 1.f : (float)cn;
            float m = (o1 + r1) / cnt;
            float var = (o2 + r2) / cnt - m*m;
            float sd = sqrtf(fmaxf(var, 1e-12f));
            __nv_bfloat162 h;
            h.x = __float2bfloat16_rn(m);
            h.y = __float2bfloat16_rn(sd);
            pw[j] = *(uint32_t*)&h;
        }
        ms4[tid*2 + q] = pk;
    }
}

// ---------------- Kernel 2: logits via warp TF32 MMA (R9 structure + cp.async W1) ----------------
// D[a=128][t=128] = W1[a,k] . attn[k,t]; warp grid 4(a) x 2(t), warp tile 32x64.
// W1 tiles: cp.async into double-buffered As (no registers, latency hidden).
// attn tiles: R9 register-prefetch + converting STS into single Bs.
__global__ void __launch_bounds__(256, 2) logits_mma_kernel(const float* __restrict__ x,
                                                            const float* __restrict__ W1,
                                                            const float* __restrict__ b1,
                                                            const float* __restrict__ W2,
                                                            const float* __restrict__ b2)
{
    extern __shared__ float sm[];
    float* AsB[2] = { sm, sm + ABUF };
    float* Bs     = sm + 2*ABUF;
    float* red    = sm + 2*ABUF + BBUF;   // [4][128]

    int tid  = threadIdx.x;
    int lane = tid & 31;
    int wid  = tid >> 5;
    int g    = lane >> 2;     // group 0..7
    int tig  = lane & 3;      // thread-in-group
    int wm   = wid >> 1;      // a quadrant 0..3
    int wn   = wid & 1;       // t half 0..1
    int b    = blockIdx.y;
    int t0   = blockIdx.x * 128;

    // Producer mappings
    int pa  = tid >> 1;            // W1: a row
    int pkh = (tid & 1) * 16;      // W1: k half
    int pk  = tid >> 3;            // attn: k row 0..31
    int pt8 = tid & 7;             // attn: 16B lane

    uint32_t asb[2] = { smem_u32(AsB[0]) + (uint32_t)(pa*A_STR + pkh)*4u,
                        smem_u32(AsB[1]) + (uint32_t)(pa*A_STR + pkh)*4u };

    // cp.async W1 chunk ch into buffer (ch&1). 4 x 16B per thread.
    auto cpa_w1 = [&](int ch) {
        const float* wrow = W1 + (size_t)pa*K3 + ch*BKC + pkh;
        uint32_t d = asb[ch & 1];
#pragma unroll
        for (int q = 0; q < 4; q++)
            cp_async16(d + q*16u, wrow + q*4);
        cp_commit();
    };

    float acc[2][8][4];
#pragma unroll
    for (int mi = 0; mi < 2; mi++)
#pragma unroll
        for (int ni = 0; ni < 8; ni++)
#pragma unroll
            for (int r = 0; r < 4; r++) acc[mi][ni][r] = 0.f;

    uint4 ast[4];   // attn staging (prefetch)

    auto stage_attn = [&](int ch) {
        int k0 = ch * BKC;
        if (k0 < Cc) {
            const uint4* p = (const uint4*)(x + ((size_t)b*Cc + k0 + pk)*(size_t)Tt + t0);
#pragma unroll
            for (int q = 0; q < 4; q++) ast[q] = __ldg(p + pt8 + q*8);
        } else {
            int crow = (k0 < 2*Cc) ? (k0 - Cc) : (k0 - 2*Cc);
            const uint4* p = (const uint4*)(g_ms + ((size_t)b*Cc + crow + pk)*(size_t)Tt + t0);
#pragma unroll
            for (int q = 0; q < 4; q++) ast[q] = __ldg(p + pt8 + q*8);
        }
    };

    // Prologue: W1(0) in flight, attn(0) staged
    cpa_w1(0);
    stage_attn(0);

    for (int ch = 0; ch < NCH; ch++) {
        int k0 = ch * BKC;

        __syncthreads();   // consumers done with Bs and with As[(ch+1)&1]

        // Issue next W1 tile (target buffer free as of the barrier above)
        if (ch + 1 < NCH) cpa_w1(ch + 1);

        // Emit attn chunk ch into Bs (tf32-rounded)
        if (k0 < Cc) {
#pragma unroll
            for (int q = 0; q < 4; q++) {
                float4 f = *(float4*)&ast[q];
                float* d = &Bs[pk*B_STR + (pt8 + q*8)*4];
                d[0] = f2tf32(f.x); d[1] = f2tf32(f.y);
                d[2] = f2tf32(f.z); d[3] = f2tf32(f.w);
            }
        } else {
            bool hi = (k0 >= 2*Cc);   // std lives in the high half
#pragma unroll
            for (int q = 0; q < 4; q++) {
                const __nv_bfloat162* h = (const __nv_bfloat162*)&ast[q];
                float* d = &Bs[pk*B_STR + (pt8 + q*8)*4];
#pragma unroll
                for (int j = 0; j < 4; j++) {
                    float v = hi ? __high2float(h[j]) : __low2float(h[j]);
                    d[j] = f2tf32(v);
                }
            }
        }

        // Drain this chunk's W1 group (leave next chunk's in flight)
        if (ch + 1 < NCH) cp_wait<1>(); else cp_wait<0>();
        __syncthreads();   // Bs + As[ch&1] visible to all

        if (ch + 1 < NCH) stage_attn(ch + 1);   // prefetch overlaps MMA

        const float* As = AsB[ch & 1];
#pragma unroll
        for (int ks = 0; ks < 4; ks++) {
            int kb = ks * 8;
            float a_fr[2][4];
#pragma unroll
            for (int mi = 0; mi < 2; mi++) {
                int ar = wm*32 + mi*16;
                a_fr[mi][0] = As[(ar + g    )*A_STR + kb + tig];
                a_fr[mi][1] = As[(ar + 8 + g)*A_STR + kb + tig];
                a_fr[mi][2] = As[(ar + g    )*A_STR + kb + tig + 4];
                a_fr[mi][3] = As[(ar + 8 + g)*A_STR + kb + tig + 4];
            }
            float b_fr[8][2];
#pragma unroll
            for (int ni = 0; ni < 8; ni++) {
                int t = wn*64 + ni*8 + g;
                b_fr[ni][0] = Bs[(kb + tig    )*B_STR + t];
                b_fr[ni][1] = Bs[(kb + tig + 4)*B_STR + t];
            }
#pragma unroll
            for (int mi = 0; mi < 2; mi++)
#pragma unroll
                for (int ni = 0; ni < 8; ni++)
                    mma_tf32(acc[mi][ni], a_fr[mi], b_fr[ni]);
        }
    }

    // Epilogue: tanh + W2 dot over a, reduce to logits[t]
    float part[16];
#pragma unroll
    for (int i = 0; i < 16; i++) part[i] = 0.f;
#pragma unroll
    for (int mi = 0; mi < 2; mi++) {
        int abase = wm*32 + mi*16;
        float b1a = __ldg(b1 + abase + g),     w2a = __ldg(W2 + abase + g);
        float b1b = __ldg(b1 + abase + 8 + g), w2b = __ldg(W2 + abase + 8 + g);
#pragma unroll
        for (int ni = 0; ni < 8; ni++) {
            part[ni*2+0] += w2a*tanhf(acc[mi][ni][0] + b1a) + w2b*tanhf(acc[mi][ni][2] + b1b);
            part[ni*2+1] += w2a*tanhf(acc[mi][ni][1] + b1a) + w2b*tanhf(acc[mi][ni][3] + b1b);
        }
    }
#pragma unroll
    for (int o = 4; o <= 16; o <<= 1)
#pragma unroll
        for (int i = 0; i < 16; i++)
            part[i] += __shfl_xor_sync(0xffffffffu, part[i], o);
    if (lane < 4) {
#pragma unroll
        for (int ni = 0; ni < 8; ni++) {
            red[wm*128 + wn*64 + ni*8 + lane*2 + 0] = part[ni*2+0];
            red[wm*128 + wn*64 + ni*8 + lane*2 + 1] = part[ni*2+1];
        }
    }
    __syncthreads();
    if (tid < 128) {
        float s = red[tid] + red[128 + tid] + red[256 + tid] + red[384 + tid];
        g_logits[b*Tt + t0 + tid] = s + __ldg(b2);
    }
}

// ---------------- Kernel 3: per-batch max, e = exp(l - max), iZ = 1/cumsum(e) ----------------
__global__ void __launch_bounds__(256) softmax_kernel()
{
    int b = blockIdx.x;
    __shared__ float ls[Tt];
    __shared__ float ws[8];
    __shared__ float red[8];
    int tid = threadIdx.x;
    int lane = tid & 31, warp = tid >> 5;

    float mx = -3.4e38f;
    for (int i = tid; i < Tt; i += 256) {
        float v = g_logits[b*Tt + i];
        ls[i] = v;
        mx = fmaxf(mx, v);
    }
#pragma unroll
    for (int d = 16; d; d >>= 1) mx = fmaxf(mx, __shfl_xor_sync(0xffffffffu, mx, d));
    if (lane == 0) red[warp] = mx;
    __syncthreads();
    if (tid == 0) {
        float m = red[0];
        for (int i = 1; i < 8; i++) m = fmaxf(m, red[i]);
        red[0] = m;
    }
    __syncthreads();
    mx = red[0];

    int base = tid * 16;
    float ev[16], l1[16];
    float c1 = 0.f;
#pragma unroll
    for (int j = 0; j < 16; j++) {
        float e = expf(ls[base + j] - mx);
        ev[j] = e; c1 += e; l1[j] = c1;
    }
    float o1 = block_excl_scan<8>(c1, ws);
    float4* e4 = (float4*)(g_e  + b*Tt + base);
    float4* z4 = (float4*)(g_iZ + b*Tt + base);
#pragma unroll
    for (int q = 0; q < 4; q++) {
        e4[q] = make_float4(ev[q*4], ev[q*4+1], ev[q*4+2], ev[q*4+3]);
        z4[q] = make_float4(1.f/(o1+l1[q*4]),   1.f/(o1+l1[q*4+1]),
                            1.f/(o1+l1[q*4+2]), 1.f/(o1+l1[q*4+3]));
    }
}

// ---------------- Kernel 4: weighted pooling (512 thr x 8 elems) ----------------
__global__ void __launch_bounds__(512, 3) pool_kernel(const float* __restrict__ x,
                                                      float* __restrict__ out)
{
    int c = blockIdx.x, b = blockIdx.y;
    size_t roff = ((size_t)b*Cc + c)*(size_t)Tt;
    int tid = threadIdx.x;
    __shared__ float ws[16];
    __shared__ float red[16];
    int lane = tid & 31, warp = tid >> 5;

    const float4* x4 = (const float4*)(x + roff);
    const float4* e4 = (const float4*)(g_e  + b*Tt);
    const float4* z4 = (const float4*)(g_iZ + b*Tt);

    float xv[8], ev[8], zv[8];
#pragma unroll
    for (int q = 0; q < 2; q++) {
        float4 f = x4[tid*2 + q]; xv[q*4]=f.x; xv[q*4+1]=f.y; xv[q*4+2]=f.z; xv[q*4+3]=f.w;
        f = e4[tid*2 + q];        ev[q*4]=f.x; ev[q*4+1]=f.y; ev[q*4+2]=f.z; ev[q*4+3]=f.w;
        f = z4[tid*2 + q];        zv[q*4]=f.x; zv[q*4+1]=f.y; zv[q*4+2]=f.z; zv[q*4+3]=f.w;
    }

    float c1 = 0.f;
#pragma unroll
    for (int j = 0; j < 8; j++) c1 += ev[j]*xv[j];
    float o1 = block_excl_scan<16>(c1, ws);

    float sum_wm = 0.f, c2 = 0.f;
    {
        float r1 = 0.f;
#pragma unroll
        for (int j = 0; j < 8; j++) {
            r1 += ev[j]*xv[j];
            float wm = (o1 + r1) * zv[j];     // zv holds 1/Z
            sum_wm += wm;
            float d = xv[j] - wm;
            c2 += ev[j]*d*d;
        }
    }
    float o2 = block_excl_scan<16>(c2, ws);

    float sum_ws = 0.f;
    {
        float r1 = 0.f, r2 = 0.f;
#pragma unroll
        for (int j = 0; j < 8; j++) {
            r1 += ev[j]*xv[j];
            float wm = (o1 + r1) * zv[j];
            float d = xv[j] - wm;
            r2 += ev[j]*d*d;
            float wv = (o2 + r2) * zv[j];
            sum_ws += sqrtf(fmaxf(wv, 1e-12f));
        }
    }

#pragma unroll
    for (int d = 16; d; d >>= 1) {
        sum_wm += __shfl_xor_sync(0xffffffffu, sum_wm, d);
        sum_ws += __shfl_xor_sync(0xffffffffu, sum_ws, d);
    }
    if (lane == 0) red[warp] = sum_wm;
    __syncthreads();
    if (tid == 0) {
        float tot_m = 0.f;
        for (int i = 0; i < 16; i++) tot_m += red[i];
        red[0] = tot_m;
    }
    __syncthreads();
    float tot_m = red[0];
    __syncthreads();
    if (lane == 0) red[warp] = sum_ws;
    __syncthreads();
    if (tid == 0) {
        float tot_s = 0.f;
        for (int i = 0; i < 16; i++) tot_s += red[i];
        const float fw = (float)(1.0 / (4096.0 + 1e-12));
        out[(size_t)b*(2*Cc) + c]      = tot_m * fw;
        out[(size_t)b*(2*Cc) + Cc + c] = tot_s * fw;
    }
}

extern "C" void kernel_launch(void* const* d_in, const int* in_sizes, int n_in,
                              void* d_out, int out_size)
{
    const float* x       = (const float*)d_in[0];
    const void*  lengths = d_in[1];            // int32 or int64, auto-detected
    const float* W1      = (const float*)d_in[2];
    const float* b1      = (const float*)d_in[3];
    const float* W2      = (const float*)d_in[4];
    const float* b2      = (const float*)d_in[5];
    float* out = (float*)d_out;

    // Idempotent, host-side, not a captured op.
    cudaFuncSetAttribute(logits_mma_kernel,
                         cudaFuncAttributeMaxDynamicSharedMemorySize, SMEM_LOGITS);

    dim3 gs(Cc, Bb);
    stats_kernel<<<gs, 512>>>(x, lengths);
    dim3 gl(Tt / 128, Bb);
    logits_mma_kernel<<<gl, 256, SMEM_LOGITS>>>(x, W1, b1, W2, b2);
    softmax_kernel<<<Bb, 256>>>();
    pool_kernel<<<gs, 512>>>(x, out);
}

// round 12
// speedup vs baseline: 1.2982x; 1.0830x over previous
#include <cuda_runtime.h>
#include <cuda_bf16.h>
#include <math.h>
#include <stdint.h>

#define Bb 8
#define Cc 1536
#define Tt 4096
#define Aa 128
#define K3 (3*Cc)   // 4608

// ---- warp-MMA logits GEMM config ----
#define A_STR 68            // W1 tile [128 a][k<=64] stride (68%32==4: conflict-free frags)
#define B_STR 136           // attn tile [64 k][t] stride (conflict-free frags)
#define ABUF (128*A_STR)    // 8704 floats
#define BBUF (64*B_STR)     // 8704 floats
#define SMEM_LOGITS ((ABUF + BBUF + 4*128)*4)   // 71680 B

// Scratch (allocation-free rule: __device__ globals)
static __device__ __nv_bfloat162 g_ms[(size_t)Bb*Cc*Tt];  // packed (mean, std)
static __device__ float g_logits[Bb*Tt];
static __device__ float g_e[Bb*Tt];
static __device__ float g_iZ[Bb*Tt];       // 1 / cumsum(e)

__device__ __forceinline__ float f2tf32(float f) {
    uint32_t r;
    asm("cvt.rna.tf32.f32 %0, %1;" : "=r"(r) : "f"(f));
    return __uint_as_float(r);
}

__device__ __forceinline__ void mma_tf32(float* d, const float* a, const float* b)
{
    asm volatile(
        "mma.sync.aligned.m16n8k8.row.col.f32.tf32.tf32.f32 "
        "{%0,%1,%2,%3}, {%4,%5,%6,%7}, {%8,%9}, {%0,%1,%2,%3};"
        : "+f"(d[0]), "+f"(d[1]), "+f"(d[2]), "+f"(d[3])
        : "r"(__float_as_uint(a[0])), "r"(__float_as_uint(a[1])),
          "r"(__float_as_uint(a[2])), "r"(__float_as_uint(a[3])),
          "r"(__float_as_uint(b[0])), "r"(__float_as_uint(b[1])));
}

// Robust lengths read (reference declares int64; JAX w/o x64 emits int32).
__device__ __forceinline__ int load_length(const void* lp, int b)
{
    const int* w = (const int*)lp;
    bool is64 = true;
#pragma unroll
    for (int i = 0; i < 4; i++)
        if (w[2*i + 1] != 0) is64 = false;
    if (is64) return (int)((const long long*)lp)[b];
    return w[b];
}

// Exclusive block scan, NW warps (NW*32 threads). ws: >= NW floats smem.
template<int NW>
__device__ __forceinline__ float block_excl_scan(float v, float* ws)
{
    int lane = threadIdx.x & 31;
    int warp = threadIdx.x >> 5;
    float incl = v;
#pragma unroll
    for (int d = 1; d < 32; d <<= 1) {
        float n = __shfl_up_sync(0xffffffffu, incl, d);
        if (lane >= d) incl += n;
    }
    __syncthreads();
    if (lane == 31) ws[warp] = incl;
    __syncthreads();
    if (warp == 0) {
        float wv = (lane < NW) ? ws[lane] : 0.f;
        float wi = wv;
#pragma unroll
        for (int d = 1; d < NW; d <<= 1) {
            float n = __shfl_up_sync(0xffffffffu, wi, d);
            if (lane >= d) wi += n;
        }
        if (lane < NW) ws[lane] = wi - wv;
    }
    __syncthreads();
    return ws[warp] + (incl - v);
}

// ---------------- Kernel 1: causal mean / std (512 thr x 8 elems, bf16x2 out) ----------------
__global__ void __launch_bounds__(512, 3) stats_kernel(const float* __restrict__ x,
                                                       const void* __restrict__ lengths)
{
    int c = blockIdx.x, b = blockIdx.y;
    size_t roff = ((size_t)b*Cc + c)*(size_t)Tt;
    const float4* row4 = (const float4*)(x + roff);
    uint4* ms4 = (uint4*)(g_ms + roff);
    int len = load_length(lengths, b);
    __shared__ float ws[16];
    int tid = threadIdx.x;
    int base = tid * 8;

    float xv[8];
#pragma unroll
    for (int q = 0; q < 2; q++) {
        float4 f = row4[tid*2 + q];
        xv[q*4+0]=f.x; xv[q*4+1]=f.y; xv[q*4+2]=f.z; xv[q*4+3]=f.w;
    }
    float c1 = 0.f, c2 = 0.f;
#pragma unroll
    for (int j = 0; j < 8; j++) {
        float v = (base + j < len) ? xv[j] : 0.f;
        c1 += v; c2 += v*v;
    }
    float o1 = block_excl_scan<16>(c1, ws);
    float o2 = block_excl_scan<16>(c2, ws);

    float r1 = 0.f, r2 = 0.f;
#pragma unroll
    for (int q = 0; q < 2; q++) {
        uint4 pk;
        uint32_t* pw = (uint32_t*)&pk;
#pragma unroll
        for (int j = 0; j < 4; j++) {
            int jj = q*4 + j;
            int t = base + jj;
            float v = (t < len) ? xv[jj] : 0.f;
            r1 += v; r2 += v*v;
            int cn = (t + 1 < len) ? (t + 1) : len;
            float cnt = (cn < 1) ? 1.f : (float)cn;
            float m = (o1 + r1) / cnt;
            float var = (o2 + r2) / cnt - m*m;
            float sd = sqrtf(fmaxf(var, 1e-12f));
            __nv_bfloat162 h;
            h.x = __float2bfloat16_rn(m);
            h.y = __float2bfloat16_rn(sd);
            pw[j] = *(uint32_t*)&h;
        }
        ms4[tid*2 + q] = pk;
    }
}

// ---------------- Kernel 2: logits via warp TF32 MMA (R9 skeleton, paired ms chunks) ----------------
// D[a=128][t=128] = W1[a,k] . attn[k,t]; warp grid 4(a) x 2(t), warp tile 32x64.
// Iterations 0..47: x chunks of 32 k-rows (as R9).
// Iterations 48..95: ONE g_ms load emits BOTH mean rows (Bs 0..31) and std rows
// (Bs 32..63); W1 supplies both 32-col groups; 8 MMA k-steps per sync period.
// g_ms read once from DRAM instead of twice.
__global__ void __launch_bounds__(256, 2) logits_mma_kernel(const float* __restrict__ x,
                                                            const float* __restrict__ W1,
                                                            const float* __restrict__ b1,
                                                            const float* __restrict__ W2,
                                                            const float* __restrict__ b2)
{
    extern __shared__ float sm[];
    float* As  = sm;                  // [128][A_STR], cols 0..63
    float* Bs  = sm + ABUF;           // [64][B_STR]
    float* red = sm + ABUF + BBUF;    // [4][128]

    int tid  = threadIdx.x;
    int lane = tid & 31;
    int wid  = tid >> 5;
    int g    = lane >> 2;     // group 0..7
    int tig  = lane & 3;      // thread-in-group
    int wm   = wid >> 1;      // a quadrant 0..3
    int wn   = wid & 1;       // t half 0..1
    int b    = blockIdx.y;
    int t0   = blockIdx.x * 128;

    // Producer mappings
    int pa  = tid >> 1;            // W1: a row
    int pkh = (tid & 1) * 16;      // W1: k half within a 32-col group
    int pk  = tid >> 3;            // attn: k row 0..31
    int pt8 = tid & 7;             // attn: 16B lane

    float acc[2][8][4];
#pragma unroll
    for (int mi = 0; mi < 2; mi++)
#pragma unroll
        for (int ni = 0; ni < 8; ni++)
#pragma unroll
            for (int r = 0; r < 4; r++) acc[mi][ni][r] = 0.f;

    uint4 ast[4];   // staging (x fp32x4 or ms bf16x2 x4 per uint4)

    auto stage = [&](int it) {
        if (it < 48) {
            const uint4* p = (const uint4*)(x + ((size_t)b*Cc + it*32 + pk)*(size_t)Tt + t0);
#pragma unroll
            for (int q = 0; q < 4; q++) ast[q] = __ldg(p + pt8 + q*8);
        } else {
            int crow = (it - 48)*32;
            const uint4* p = (const uint4*)(g_ms + ((size_t)b*Cc + crow + pk)*(size_t)Tt + t0);
#pragma unroll
            for (int q = 0; q < 4; q++) ast[q] = __ldg(p + pt8 + q*8);
        }
    };

    stage(0);

    for (int it = 0; it < 96; it++) {
        bool p2 = (it >= 48);

        // W1 staging (issued before barrier: latency overlaps barrier wait, as R9)
        float4 wv[8];
        if (!p2) {
            const float4* wrow = (const float4*)(W1 + (size_t)pa*K3 + it*32 + pkh);
#pragma unroll
            for (int q = 0; q < 4; q++) wv[q] = __ldg(wrow + q);
        } else {
            int crow = (it - 48)*32;
            const float4* wrm = (const float4*)(W1 + (size_t)pa*K3 + Cc   + crow + pkh);
            const float4* wrs = (const float4*)(W1 + (size_t)pa*K3 + 2*Cc + crow + pkh);
#pragma unroll
            for (int q = 0; q < 4; q++) { wv[q] = __ldg(wrm + q); wv[4+q] = __ldg(wrs + q); }
        }

        __syncthreads();   // consumers done with previous As/Bs

        // Emit Bs
        if (!p2) {
#pragma unroll
            for (int q = 0; q < 4; q++) {
                float4 f = *(float4*)&ast[q];
                float* d = &Bs[pk*B_STR + (pt8 + q*8)*4];
                d[0] = f2tf32(f.x); d[1] = f2tf32(f.y);
                d[2] = f2tf32(f.z); d[3] = f2tf32(f.w);
            }
        } else {
#pragma unroll
            for (int q = 0; q < 4; q++) {
                const __nv_bfloat162* h = (const __nv_bfloat162*)&ast[q];
                float* dm = &Bs[pk*B_STR        + (pt8 + q*8)*4];
                float* ds = &Bs[(32+pk)*B_STR   + (pt8 + q*8)*4];
#pragma unroll
                for (int j = 0; j < 4; j++) {
                    dm[j] = f2tf32(__low2float(h[j]));
                    ds[j] = f2tf32(__high2float(h[j]));
                }
            }
        }
        // Emit As (cols 0..31 = first group; cols 32..63 = std group in phase 2)
#pragma unroll
        for (int q = 0; q < 4; q++) {
            float* d = &As[pa*A_STR + pkh + q*4];
            d[0] = f2tf32(wv[q].x); d[1] = f2tf32(wv[q].y);
            d[2] = f2tf32(wv[q].z); d[3] = f2tf32(wv[q].w);
        }
        if (p2) {
#pragma unroll
            for (int q = 0; q < 4; q++) {
                float* d = &As[pa*A_STR + 32 + pkh + q*4];
                d[0] = f2tf32(wv[4+q].x); d[1] = f2tf32(wv[4+q].y);
                d[2] = f2tf32(wv[4+q].z); d[3] = f2tf32(wv[4+q].w);
            }
        }
        __syncthreads();   // tiles visible

        if (it + 1 < 96) stage(it + 1);   // prefetch overlaps MMA (16 regs, as R9)

        // MMA: 4 k-steps (phase 1) or 8 (phase 2)
#pragma unroll
        for (int ks = 0; ks < 8; ks++) {
            if (!p2 && ks >= 4) break;
            int kb = ks * 8;
            float a_fr[2][4];
#pragma unroll
            for (int mi = 0; mi < 2; mi++) {
                int ar = wm*32 + mi*16;
                a_fr[mi][0] = As[(ar + g    )*A_STR + kb + tig];
                a_fr[mi][1] = As[(ar + 8 + g)*A_STR + kb + tig];
                a_fr[mi][2] = As[(ar + g    )*A_STR + kb + tig + 4];
                a_fr[mi][3] = As[(ar + 8 + g)*A_STR + kb + tig + 4];
            }
            float b_fr[8][2];
#pragma unroll
            for (int ni = 0; ni < 8; ni++) {
                int t = wn*64 + ni*8 + g;
                b_fr[ni][0] = Bs[(kb + tig    )*B_STR + t];
                b_fr[ni][1] = Bs[(kb + tig + 4)*B_STR + t];
            }
#pragma unroll
            for (int mi = 0; mi < 2; mi++)
#pragma unroll
                for (int ni = 0; ni < 8; ni++)
                    mma_tf32(acc[mi][ni], a_fr[mi], b_fr[ni]);
        }
    }

    // Epilogue: tanh + W2 dot over a, reduce to logits[t]
    float part[16];
#pragma unroll
    for (int i = 0; i < 16; i++) part[i] = 0.f;
#pragma unroll
    for (int mi = 0; mi < 2; mi++) {
        int abase = wm*32 + mi*16;
        float b1a = __ldg(b1 + abase + g),     w2a = __ldg(W2 + abase + g);
        float b1b = __ldg(b1 + abase + 8 + g), w2b = __ldg(W2 + abase + 8 + g);
#pragma unroll
        for (int ni = 0; ni < 8; ni++) {
            part[ni*2+0] += w2a*tanhf(acc[mi][ni][0] + b1a) + w2b*tanhf(acc[mi][ni][2] + b1b);
            part[ni*2+1] += w2a*tanhf(acc[mi][ni][1] + b1a) + w2b*tanhf(acc[mi][ni][3] + b1b);
        }
    }
#pragma unroll
    for (int o = 4; o <= 16; o <<= 1)
#pragma unroll
        for (int i = 0; i < 16; i++)
            part[i] += __shfl_xor_sync(0xffffffffu, part[i], o);
    if (lane < 4) {
#pragma unroll
        for (int ni = 0; ni < 8; ni++) {
            red[wm*128 + wn*64 + ni*8 + lane*2 + 0] = part[ni*2+0];
            red[wm*128 + wn*64 + ni*8 + lane*2 + 1] = part[ni*2+1];
        }
    }
    __syncthreads();
    if (tid < 128) {
        float s = red[tid] + red[128 + tid] + red[256 + tid] + red[384 + tid];
        g_logits[b*Tt + t0 + tid] = s + __ldg(b2);
    }
}

// ---------------- Kernel 3: per-batch max, e = exp(l - max), iZ = 1/cumsum(e) ----------------
__global__ void __launch_bounds__(256) softmax_kernel()
{
    int b = blockIdx.x;
    __shared__ float ls[Tt];
    __shared__ float ws[8];
    __shared__ float red[8];
    int tid = threadIdx.x;
    int lane = tid & 31, warp = tid >> 5;

    float mx = -3.4e38f;
    for (int i = tid; i < Tt; i += 256) {
        float v = g_logits[b*Tt + i];
        ls[i] = v;
        mx = fmaxf(mx, v);
    }
#pragma unroll
    for (int d = 16; d; d >>= 1) mx = fmaxf(mx, __shfl_xor_sync(0xffffffffu, mx, d));
    if (lane == 0) red[warp] = mx;
    __syncthreads();
    if (tid == 0) {
        float m = red[0];
        for (int i = 1; i < 8; i++) m = fmaxf(m, red[i]);
        red[0] = m;
    }
    __syncthreads();
    mx = red[0];

    int base = tid * 16;
    float ev[16], l1[16];
    float c1 = 0.f;
#pragma unroll
    for (int j = 0; j < 16; j++) {
        float e = expf(ls[base + j] - mx);
        ev[j] = e; c1 += e; l1[j] = c1;
    }
    float o1 = block_excl_scan<8>(c1, ws);
    float4* e4 = (float4*)(g_e  + b*Tt + base);
    float4* z4 = (float4*)(g_iZ + b*Tt + base);
#pragma unroll
    for (int q = 0; q < 4; q++) {
        e4[q] = make_float4(ev[q*4], ev[q*4+1], ev[q*4+2], ev[q*4+3]);
        z4[q] = make_float4(1.f/(o1+l1[q*4]),   1.f/(o1+l1[q*4+1]),
                            1.f/(o1+l1[q*4+2]), 1.f/(o1+l1[q*4+3]));
    }
}

// ---------------- Kernel 4: weighted pooling (512 thr x 8 elems) ----------------
__global__ void __launch_bounds__(512, 3) pool_kernel(const float* __restrict__ x,
                                                      float* __restrict__ out)
{
    int c = blockIdx.x, b = blockIdx.y;
    size_t roff = ((size_t)b*Cc + c)*(size_t)Tt;
    int tid = threadIdx.x;
    __shared__ float ws[16];
    __shared__ float red[16];
    int lane = tid & 31, warp = tid >> 5;

    const float4* x4 = (const float4*)(x + roff);
    const float4* e4 = (const float4*)(g_e  + b*Tt);
    const float4* z4 = (const float4*)(g_iZ + b*Tt);

    float xv[8], ev[8], zv[8];
#pragma unroll
    for (int q = 0; q < 2; q++) {
        float4 f = x4[tid*2 + q]; xv[q*4]=f.x; xv[q*4+1]=f.y; xv[q*4+2]=f.z; xv[q*4+3]=f.w;
        f = e4[tid*2 + q];        ev[q*4]=f.x; ev[q*4+1]=f.y; ev[q*4+2]=f.z; ev[q*4+3]=f.w;
        f = z4[tid*2 + q];        zv[q*4]=f.x; zv[q*4+1]=f.y; zv[q*4+2]=f.z; zv[q*4+3]=f.w;
    }

    float c1 = 0.f;
#pragma unroll
    for (int j = 0; j < 8; j++) c1 += ev[j]*xv[j];
    float o1 = block_excl_scan<16>(c1, ws);

    float sum_wm = 0.f, c2 = 0.f;
    {
        float r1 = 0.f;
#pragma unroll
        for (int j = 0; j < 8; j++) {
            r1 += ev[j]*xv[j];
            float wm = (o1 + r1) * zv[j];     // zv holds 1/Z
            sum_wm += wm;
            float d = xv[j] - wm;
            c2 += ev[j]*d*d;
        }
    }
    float o2 = block_excl_scan<16>(c2, ws);

    float sum_ws = 0.f;
    {
        float r1 = 0.f, r2 = 0.f;
#pragma unroll
        for (int j = 0; j < 8; j++) {
            r1 += ev[j]*xv[j];
            float wm = (o1 + r1) * zv[j];
            float d = xv[j] - wm;
            r2 += ev[j]*d*d;
            float wv = (o2 + r2) * zv[j];
            sum_ws += sqrtf(fmaxf(wv, 1e-12f));
        }
    }

#pragma unroll
    for (int d = 16; d; d >>= 1) {
        sum_wm += __shfl_xor_sync(0xffffffffu, sum_wm, d);
        sum_ws += __shfl_xor_sync(0xffffffffu, sum_ws, d);
    }
    if (lane == 0) red[warp] = sum_wm;
    __syncthreads();
    if (tid == 0) {
        float tot_m = 0.f;
        for (int i = 0; i < 16; i++) tot_m += red[i];
        red[0] = tot_m;
    }
    __syncthreads();
    float tot_m = red[0];
    __syncthreads();
    if (lane == 0) red[warp] = sum_ws;
    __syncthreads();
    if (tid == 0) {
        float tot_s = 0.f;
        for (int i = 0; i < 16; i++) tot_s += red[i];
        const float fw = (float)(1.0 / (4096.0 + 1e-12));
        out[(size_t)b*(2*Cc) + c]      = tot_m * fw;
        out[(size_t)b*(2*Cc) + Cc + c] = tot_s * fw;
    }
}

extern "C" void kernel_launch(void* const* d_in, const int* in_sizes, int n_in,
                              void* d_out, int out_size)
{
    const float* x       = (const float*)d_in[0];
    const void*  lengths = d_in[1];            // int32 or int64, auto-detected
    const float* W1      = (const float*)d_in[2];
    const float* b1      = (const float*)d_in[3];
    const float* W2      = (const float*)d_in[4];
    const float* b2      = (const float*)d_in[5];
    float* out = (float*)d_out;

    // Idempotent, host-side, not a captured op.
    cudaFuncSetAttribute(logits_mma_kernel,
                         cudaFuncAttributeMaxDynamicSharedMemorySize, SMEM_LOGITS);

    dim3 gs(Cc, Bb);
    stats_kernel<<<gs, 512>>>(x, lengths);
    dim3 gl(Tt / 128, Bb);
    logits_mma_kernel<<<gl, 256, SMEM_LOGITS>>>(x, W1, b1, W2, b2);
    softmax_kernel<<<Bb, 256>>>();
    pool_kernel<<<gs, 512>>>(x, out);
}